// round 5
// baseline (speedup 1.0000x reference)
#include <cuda_runtime.h>
#include <cstdint>
#include <math.h>

#define N_NODES   100000
#define N_EDGES   200000
#define NNZ       2000000
#define DIM       64
#define HID       32
#define K_KEEP    1000000

// ---------------- device scratch (no allocations allowed) ----------------
struct Ctrl {
    unsigned p1, p2, Tbits;
    int rank;
    int skip;
    int ib;
    int cutoff;
};

__device__ __align__(16) float g_xa[N_NODES * HID];   // x @ W1[:64] + b1
__device__ __align__(16) float g_xb[N_NODES * HID];   // x @ W1[64:]
__device__ __align__(16) float g_eb[N_EDGES * HID];   // segment sums of xb
__device__ int      g_cnt[N_EDGES];
__device__ float    g_sum_p[N_EDGES];
__device__ float    g_sum_s[N_EDGES];
__device__ int      g_cand[NNZ];
__device__ unsigned g_cbits[NNZ];
__device__ int      g_ncand;
__device__ unsigned g_hist[5][2048];
__device__ Ctrl     g_ctrl;

// ---------------- pre-zero small state (must precede counting) ----------------
__global__ void k_pre() {
    int tid = blockIdx.x * blockDim.x + threadIdx.x;
    int nt  = gridDim.x * blockDim.x;
    for (int i = tid; i < N_EDGES; i += nt) {
        g_cnt[i] = 0; g_sum_p[i] = 0.0f; g_sum_s[i] = 0.0f;
    }
    for (int i = tid; i < 5 * 2048; i += nt) ((unsigned*)g_hist)[i] = 0u;
    if (tid == 0) {
        g_ctrl.p1 = 0; g_ctrl.p2 = 0; g_ctrl.Tbits = 0;
        g_ctrl.rank = 0; g_ctrl.skip = 0; g_ctrl.ib = 0; g_ctrl.cutoff = 0;
        g_ncand = 0;
    }
}

// ---------------- fused: proj (blocks 0..511) | zero eb (512..639) | count E (640..767) ----------------
#define PROJ_BLKS 512
#define ZERO_BLKS 128
#define CNT_BLKS  128
__global__ void k_init(const float* __restrict__ x,
                       const float* __restrict__ W1,
                       const float* __restrict__ b1,
                       const int* __restrict__ E) {
    int b = blockIdx.x;
    if (b < PROJ_BLKS) {
        __shared__ float sW[128 * 32];
        for (int i = threadIdx.x; i < 128 * 32; i += blockDim.x) sW[i] = W1[i];
        __syncthreads();
        int lane = threadIdx.x & 31;
        int warp = threadIdx.x >> 5;
        int wpb  = blockDim.x >> 5;
        float bb = b1[lane];
        for (int row = b * wpb + warp; row < N_NODES; row += PROJ_BLKS * wpb) {
            float x0 = x[row * 64 + lane];
            float x1 = x[row * 64 + 32 + lane];
            float aa = bb, ab = 0.0f;
#pragma unroll
            for (int k = 0; k < 32; k++) {
                float xv = __shfl_sync(0xffffffffu, x0, k);
                aa += xv * sW[k * 32 + lane];
                ab += xv * sW[(64 + k) * 32 + lane];
            }
#pragma unroll
            for (int k = 0; k < 32; k++) {
                float xv = __shfl_sync(0xffffffffu, x1, k);
                aa += xv * sW[(32 + k) * 32 + lane];
                ab += xv * sW[(96 + k) * 32 + lane];
            }
            g_xa[row * 32 + lane] = aa;
            g_xb[row * 32 + lane] = ab;
        }
    } else if (b < PROJ_BLKS + ZERO_BLKS) {
        int tid = (b - PROJ_BLKS) * blockDim.x + threadIdx.x;
        int nt  = ZERO_BLKS * blockDim.x;
        float4 z4 = make_float4(0.f, 0.f, 0.f, 0.f);
        float4* eb4 = reinterpret_cast<float4*>(g_eb);
        for (int i = tid; i < N_EDGES * HID / 4; i += nt) eb4[i] = z4;
    } else {
        int tid = (b - PROJ_BLKS - ZERO_BLKS) * blockDim.x + threadIdx.x;
        int nt  = CNT_BLKS * blockDim.x;
        for (int t = tid; t < NNZ / 4; t += nt) {
            int4 e4 = reinterpret_cast<const int4*>(E)[t];
            atomicAdd(&g_cnt[e4.x], 1);
            atomicAdd(&g_cnt[e4.y], 1);
            atomicAdd(&g_cnt[e4.z], 1);
            atomicAdd(&g_cnt[e4.w], 1);
        }
    }
}

// ---------------- scatter xb into per-edge sums (4 lanes / nnz, 2x red.v4 each) ----------------
__global__ void k_scatter(const int* __restrict__ V, const int* __restrict__ E) {
    int tid = blockIdx.x * blockDim.x + threadIdx.x;
    int g   = tid >> 2;
    int sub = tid & 3;
    if (g >= NNZ) return;
    int v = V[g], e = E[g];
    const float4* src = reinterpret_cast<const float4*>(&g_xb[v * 32]) + sub * 2;
    float4 v0 = src[0];
    float4 v1 = src[1];
    float* dst = &g_eb[e * 32 + sub * 8];
    asm volatile("red.global.add.v4.f32 [%0], {%1,%2,%3,%4};"
                 :: "l"(dst), "f"(v0.x), "f"(v0.y), "f"(v0.z), "f"(v0.w) : "memory");
    asm volatile("red.global.add.v4.f32 [%0], {%1,%2,%3,%4};"
                 :: "l"(dst + 4), "f"(v1.x), "f"(v1.y), "f"(v1.z), "f"(v1.w) : "memory");
}

// ---------------- fused MLP: probs + edge prob sums (4 lanes / nnz) ----------------
__global__ void k_logits(const int* __restrict__ V, const int* __restrict__ E,
                         const float* __restrict__ W2, const float* __restrict__ b2,
                         float* __restrict__ out_probs) {
    int tid = blockIdx.x * blockDim.x + threadIdx.x;
    int g   = tid >> 2;
    int sub = tid & 3;
    if (g >= NNZ) return;
    int v = V[g], e = E[g];
    int c = g_cnt[e];
    float ic = 1.0f / (float)(c > 1 ? c : 1);
    const float4* pa = reinterpret_cast<const float4*>(&g_xa[v * 32]) + sub * 2;
    const float4* pm = reinterpret_cast<const float4*>(&g_eb[e * 32]) + sub * 2;
    const float4* pw = reinterpret_cast<const float4*>(W2) + sub * 2;
    float4 a0 = pa[0], a1 = pa[1];
    float4 m0 = pm[0], m1 = pm[1];
    float4 w0 = pw[0], w1 = pw[1];
    float part =
        fmaxf(a0.x + m0.x * ic, 0.0f) * w0.x +
        fmaxf(a0.y + m0.y * ic, 0.0f) * w0.y +
        fmaxf(a0.z + m0.z * ic, 0.0f) * w0.z +
        fmaxf(a0.w + m0.w * ic, 0.0f) * w0.w +
        fmaxf(a1.x + m1.x * ic, 0.0f) * w1.x +
        fmaxf(a1.y + m1.y * ic, 0.0f) * w1.y +
        fmaxf(a1.z + m1.z * ic, 0.0f) * w1.z +
        fmaxf(a1.w + m1.w * ic, 0.0f) * w1.w;
    part += __shfl_xor_sync(0xffffffffu, part, 2);
    part += __shfl_xor_sync(0xffffffffu, part, 1);
    if (sub == 0) {
        float z = part + b2[0];
        float p = 1.0f / (1.0f + __expf(-z));
        out_probs[g] = p;
        asm volatile("red.global.add.f32 [%0], %1;" :: "l"(&g_sum_p[e]), "f"(p) : "memory");
    }
}

// ---------------- phase-0 histogram (full probs) ----------------
__global__ void k_hist0(const float* __restrict__ probs) {
    __shared__ unsigned sh[2048];
    for (int i = threadIdx.x; i < 2048; i += blockDim.x) sh[i] = 0u;
    __syncthreads();
    int tid = blockIdx.x * blockDim.x + threadIdx.x;
    int nt  = gridDim.x * blockDim.x;
    for (int t = tid; t < NNZ / 4; t += nt) {
        float4 p4 = reinterpret_cast<const float4*>(probs)[t];
        atomicAdd(&sh[__float_as_uint(p4.x) >> 21], 1u);
        atomicAdd(&sh[__float_as_uint(p4.y) >> 21], 1u);
        atomicAdd(&sh[__float_as_uint(p4.z) >> 21], 1u);
        atomicAdd(&sh[__float_as_uint(p4.w) >> 21], 1u);
    }
    __syncthreads();
    for (int i = threadIdx.x; i < 2048; i += blockDim.x) {
        unsigned vv = sh[i];
        if (vv) atomicAdd(&g_hist[0][i], vv);
    }
}

// ---------------- compaction: collect phase-1 candidates + phase-1 hist ----------------
__global__ void k_compact(const float* __restrict__ probs) {
    __shared__ unsigned sh[2048];
    for (int i = threadIdx.x; i < 2048; i += blockDim.x) sh[i] = 0u;
    __syncthreads();
    unsigned p1 = g_ctrl.p1;
    int tid = blockIdx.x * blockDim.x + threadIdx.x;
    int nt  = gridDim.x * blockDim.x;
    int iters = (NNZ + nt - 1) / nt;
    int lane = threadIdx.x & 31;
    for (int it = 0; it < iters; it++) {
        int i = tid + it * nt;
        bool mt = false;
        unsigned bits = 0;
        if (i < NNZ) {
            bits = __float_as_uint(probs[i]);
            mt = ((bits >> 21) == p1);
        }
        unsigned ball = __ballot_sync(0xffffffffu, mt);
        if (ball) {
            int cnt = __popc(ball);
            int base = 0;
            if (lane == 0) base = atomicAdd(&g_ncand, cnt);
            base = __shfl_sync(0xffffffffu, base, 0);
            if (mt) {
                int off = __popc(ball & ((1u << lane) - 1u));
                g_cand[base + off]  = i;
                g_cbits[base + off] = bits;
                atomicAdd(&sh[(bits >> 10) & 2047u], 1u);
            }
        }
    }
    __syncthreads();
    for (int i = threadIdx.x; i < 2048; i += blockDim.x) {
        unsigned vv = sh[i];
        if (vv) atomicAdd(&g_hist[1][i], vv);
    }
}

// ---------------- candidate-domain histograms (phases 2..4) ----------------
__global__ void k_chist(int phase) {
    __shared__ unsigned sh[2048];
    for (int i = threadIdx.x; i < 2048; i += blockDim.x) sh[i] = 0u;
    __syncthreads();
    if (phase >= 3 && g_ctrl.skip) return;
    unsigned p2 = g_ctrl.p2, Tb = g_ctrl.Tbits;
    int ib = g_ctrl.ib;
    int n  = g_ncand;
    int tid = blockIdx.x * blockDim.x + threadIdx.x;
    int nt  = gridDim.x * blockDim.x;
    for (int c = tid; c < n; c += nt) {
        unsigned bits = g_cbits[c];
        int b = -1;
        if (phase == 2)      { if ((bits >> 10) == p2) b = (int)(bits & 1023u); }
        else if (phase == 3) { if (bits == Tb) b = g_cand[c] >> 11; }
        else                 { int i = g_cand[c];
                               if (bits == Tb && (i >> 11) == ib) b = i & 2047; }
        if (b >= 0) atomicAdd(&sh[b], 1u);
    }
    __syncthreads();
    for (int i = threadIdx.x; i < 2048; i += blockDim.x) {
        unsigned vv = sh[i];
        if (vv) atomicAdd(&g_hist[phase][i], vv);
    }
}

// ---------------- selection: scan + pick bucket ----------------
__global__ void k_scan(int phase) {
    __shared__ unsigned sA[2048], sB[2048];
    if (phase >= 3 && g_ctrl.skip) return;
    int n   = (phase == 2 || phase == 3) ? 1024 : 2048;
    int tid = threadIdx.x;  // blockDim = 1024
    const unsigned* hist = g_hist[phase];
    for (int i = tid; i < n; i += 1024) sA[i] = hist[i];
    __syncthreads();
    bool desc = (phase <= 2);
    unsigned *in = sA, *out = sB;
    for (int off = 1; off < n; off <<= 1) {
        for (int i = tid; i < n; i += 1024) {
            unsigned add = 0;
            if (desc) { if (i + off < n) add = in[i + off]; }
            else      { if (i >= off)    add = in[i - off]; }
            out[i] = in[i] + add;
        }
        __syncthreads();
        unsigned* t = in; in = out; out = t;
    }
    int rank = (phase == 0) ? K_KEEP : g_ctrl.rank;
    for (int i = tid; i < n; i += 1024) {
        bool hit;
        unsigned adj;
        if (desc) {
            unsigned nxt = (i + 1 < n) ? in[i + 1] : 0u;
            hit = ((int)in[i] >= rank) && ((int)nxt < rank);
            adj = nxt;
        } else {
            unsigned prv = (i > 0) ? in[i - 1] : 0u;
            hit = ((int)in[i] >= rank) && ((int)prv < rank);
            adj = prv;
        }
        if (hit) {
            if (phase == 0)      { g_ctrl.p1 = (unsigned)i; g_ctrl.rank = rank - (int)adj; }
            else if (phase == 1) { g_ctrl.p2 = (g_ctrl.p1 << 11) | (unsigned)i; g_ctrl.rank = rank - (int)adj; }
            else if (phase == 2) {
                g_ctrl.Tbits = (g_ctrl.p2 << 10) | (unsigned)i;
                int r   = rank - (int)adj;
                int neq = (int)(in[i] - adj);
                if (r >= neq) { g_ctrl.skip = 1; g_ctrl.cutoff = 0x7fffffff; }
                else          { g_ctrl.skip = 0; g_ctrl.rank = r; }
            }
            else if (phase == 3) { g_ctrl.ib = i; g_ctrl.rank = rank - (int)adj; }
            else                 { g_ctrl.cutoff = (g_ctrl.ib << 11) | i; }
        }
    }
}

// ---------------- hard/soft mask + edge soft sums (8 nnz / thread) ----------------
__global__ void k_mask(const int* __restrict__ E, const float* __restrict__ probs,
                       float* __restrict__ soft, float* __restrict__ hard) {
    int t = blockIdx.x * blockDim.x + threadIdx.x;
    if (t >= NNZ / 8) return;
    unsigned T = g_ctrl.Tbits;
    int cut = g_ctrl.cutoff;
#pragma unroll
    for (int half = 0; half < 2; half++) {
        int idx = t * 2 + half;
        float4 p4 = reinterpret_cast<const float4*>(probs)[idx];
        int4   e4 = reinterpret_cast<const int4*>(E)[idx];
        int base = idx * 4;
        float pv[4] = {p4.x, p4.y, p4.z, p4.w};
        int   ev[4] = {e4.x, e4.y, e4.z, e4.w};
        float sf[4], hf[4];
#pragma unroll
        for (int j = 0; j < 4; j++) {
            unsigned bits = __float_as_uint(pv[j]);
            bool h = (bits > T) || (bits == T && (base + j) <= cut);
            hf[j] = h ? 1.0f : 0.0f;
            sf[j] = h ? ((1.0f - pv[j]) + pv[j]) : 0.0f;
            if (h)
                asm volatile("red.global.add.f32 [%0], %1;"
                             :: "l"(&g_sum_s[ev[j]]), "f"(sf[j]) : "memory");
        }
        reinterpret_cast<float4*>(soft)[idx] = make_float4(sf[0], sf[1], sf[2], sf[3]);
        reinterpret_cast<float4*>(hard)[idx] = make_float4(hf[0], hf[1], hf[2], hf[3]);
    }
}

// ---------------- edge outputs (vectorized) ----------------
__global__ void k_edges(float* __restrict__ ep, float* __restrict__ es, float* __restrict__ eh) {
    int t = blockIdx.x * blockDim.x + threadIdx.x;
    if (t >= N_EDGES / 4) return;
    int4   c4 = reinterpret_cast<const int4*>(g_cnt)[t];
    float4 sp = reinterpret_cast<const float4*>(g_sum_p)[t];
    float4 ss = reinterpret_cast<const float4*>(g_sum_s)[t];
    float c0 = (float)(c4.x > 1 ? c4.x : 1);
    float c1 = (float)(c4.y > 1 ? c4.y : 1);
    float c2 = (float)(c4.z > 1 ? c4.z : 1);
    float c3 = (float)(c4.w > 1 ? c4.w : 1);
    reinterpret_cast<float4*>(ep)[t] = make_float4(sp.x / c0, sp.y / c1, sp.z / c2, sp.w / c3);
    reinterpret_cast<float4*>(es)[t] = make_float4(ss.x / c0, ss.y / c1, ss.z / c2, ss.w / c3);
    reinterpret_cast<float4*>(eh)[t] = make_float4(ss.x > 0.f ? 1.f : 0.f, ss.y > 0.f ? 1.f : 0.f,
                                                   ss.z > 0.f ? 1.f : 0.f, ss.w > 0.f ? 1.f : 0.f);
}

// ---------------- launcher ----------------
extern "C" void kernel_launch(void* const* d_in, const int* in_sizes, int n_in,
                              void* d_out, int out_size) {
    const float* x  = (const float*)d_in[0];
    const int*   V  = (const int*)d_in[1];
    const int*   E  = (const int*)d_in[2];
    const float* W1 = (const float*)d_in[3];
    const float* b1 = (const float*)d_in[4];
    const float* W2 = (const float*)d_in[5];
    const float* b2 = (const float*)d_in[6];

    float* out   = (float*)d_out;
    float* probs = out;
    float* soft  = out + NNZ;
    float* hard  = out + 2 * NNZ;
    float* ep    = out + 3 * NNZ;
    float* es    = ep + N_EDGES;
    float* eh    = es + N_EDGES;

    k_pre<<<256, 256>>>();
    k_init<<<PROJ_BLKS + ZERO_BLKS + CNT_BLKS, 256>>>(x, W1, b1, E);
    k_scatter<<<(NNZ * 4 + 255) / 256, 256>>>(V, E);
    k_logits<<<(NNZ * 4 + 255) / 256, 256>>>(V, E, W2, b2, probs);   // profiled slot
    k_hist0<<<512, 256>>>(probs);
    k_scan<<<1, 1024>>>(0);
    k_compact<<<512, 256>>>(probs);
    k_scan<<<1, 1024>>>(1);
    k_chist<<<256, 256>>>(2);
    k_scan<<<1, 1024>>>(2);
    k_chist<<<256, 256>>>(3);
    k_scan<<<1, 1024>>>(3);
    k_chist<<<256, 256>>>(4);
    k_scan<<<1, 1024>>>(4);
    k_mask<<<(NNZ / 8 + 255) / 256, 256>>>(E, probs, soft, hard);
    k_edges<<<(N_EDGES / 4 + 255) / 256, 256>>>(ep, es, eh);
}